// round 1
// baseline (speedup 1.0000x reference)
#include <cuda_runtime.h>
#include <math.h>

#define B_ 8
#define C_ 384
#define H_ 14
#define W_ 14
#define N_ 196
#define HEADS_ 12
#define RH_ 7
#define RW_ 7
#define S_ 49
#define ST_ 58
#define M_ (B_*N_)     // 1568
#define FSTR 385       // padded feats row stride (conflict-free)

#define CDIV(a,b) (((a)+(b)-1)/(b))

// ---------------- scratch (device globals; no allocation allowed) ----------
__device__ float g_xh[M_*C_];
__device__ float g_q [M_*C_];
__device__ float g_t1[M_*C_];
__device__ float g_t2[B_*S_*C_];
__device__ float g_offp[B_*S_*2*N_];
__device__ float g_co[M_*18];
__device__ float g_qk[(size_t)M_*HEADS_*C_];
__device__ float g_fa[(size_t)M_*HEADS_*C_];
__device__ float g_ov[M_*C_];
__device__ float g_y [M_*C_];

__constant__ float c_offy[9] = {0.f,-1.f,-1.f,-1.f,0.f,1.f,1.f,1.f,0.f};
__constant__ float c_offx[9] = {-1.f,-1.f,0.f,1.f,1.f,1.f,0.f,-1.f,0.f};

__device__ __forceinline__ float gelu_f(float v){
    return 0.5f*v*(1.0f+erff(v*0.70710678118654752f));
}

// ---------------- generic batched tiled GEMM:  C = A * op(B) (+bias)(+ep) --
// A row-major [M,K] (lda). If !transB: B[k,n]=Bm[k*ldb+n]. If transB: B[k,n]=Bm[n*ldb+k].
// ep: 0 none, 1 gelu, 2 tanh*scale
__global__ __launch_bounds__(256) void gemm_kernel(
    const float* __restrict__ A, const float* __restrict__ Bm,
    const float* __restrict__ bias, float* __restrict__ C,
    int M, int N, int K, int lda, int ldb, int ldc,
    long long aB, long long bB, long long cB, int biasB,
    int transB, int ep, float scale)
{
    const int BM=64, BN=64, BK=16;
    __shared__ float As[BK][BM+1];
    __shared__ float Bs[BK][BN+1];
    A  += (long long)blockIdx.z * aB;
    Bm += (long long)blockIdx.z * bB;
    C  += (long long)blockIdx.z * cB;
    if (bias) bias += (long long)blockIdx.z * biasB;
    int m0 = blockIdx.y*BM, n0 = blockIdx.x*BN;
    int tid = threadIdx.x;
    int tm = (tid>>4)*4, tn = (tid&15)*4;
    float acc[4][4];
    #pragma unroll
    for(int i=0;i<4;i++)
      #pragma unroll
      for(int j=0;j<4;j++) acc[i][j]=0.f;

    for (int k0=0;k0<K;k0+=BK){
        {
            int r = tid>>2, kc=(tid&3)*4;
            int mm = m0+r;
            #pragma unroll
            for (int j=0;j<4;j++){
                int kk = k0+kc+j;
                As[kc+j][r] = (mm<M && kk<K) ? A[(long long)mm*lda + kk] : 0.f;
            }
        }
        if (!transB){
            int r = tid>>4, nc=(tid&15)*4;
            int kk = k0+r;
            #pragma unroll
            for (int j=0;j<4;j++){
                int nn = n0+nc+j;
                Bs[r][nc+j] = (kk<K && nn<N) ? Bm[(long long)kk*ldb + nn] : 0.f;
            }
        } else {
            int r = tid>>2, kc=(tid&3)*4;
            int nn = n0+r;
            #pragma unroll
            for (int j=0;j<4;j++){
                int kk = k0+kc+j;
                Bs[kc+j][r] = (nn<N && kk<K) ? Bm[(long long)nn*ldb + kk] : 0.f;
            }
        }
        __syncthreads();
        #pragma unroll
        for (int k=0;k<BK;k++){
            float a[4], bb[4];
            #pragma unroll
            for (int i=0;i<4;i++) a[i]=As[k][tm+i];
            #pragma unroll
            for (int j=0;j<4;j++) bb[j]=Bs[k][tn+j];
            #pragma unroll
            for (int i=0;i<4;i++)
                #pragma unroll
                for (int j=0;j<4;j++) acc[i][j] += a[i]*bb[j];
        }
        __syncthreads();
    }
    #pragma unroll
    for (int i=0;i<4;i++){
        int mm = m0+tm+i;
        if (mm>=M) continue;
        #pragma unroll
        for (int j=0;j<4;j++){
            int nn = n0+tn+j;
            if (nn>=N) continue;
            float v = acc[i][j];
            if (bias) v += bias[nn];
            if (ep==1) v = gelu_f(v);
            else if (ep==2) v = tanhf(v)*scale;
            C[(long long)mm*ldc + nn] = v;
        }
    }
}

// ---------------- batched matrix transpose: in [R,Cc] -> out [Cc,R] --------
__global__ __launch_bounds__(256) void transpose_kernel(
    const float* __restrict__ in, float* __restrict__ out, int R, int Cc)
{
    __shared__ float tile[32][33];
    const float* inb = in + (size_t)blockIdx.z * R * Cc;
    float* outb = out + (size_t)blockIdx.z * R * Cc;
    int bx = blockIdx.x*32, by = blockIdx.y*32;
    int tx = threadIdx.x, ty = threadIdx.y;
    #pragma unroll
    for (int i=0;i<32;i+=8){
        int r = by+ty+i, c = bx+tx;
        if (r<R && c<Cc) tile[ty+i][tx] = inb[(size_t)r*Cc + c];
    }
    __syncthreads();
    #pragma unroll
    for (int i=0;i<32;i+=8){
        int c = bx+ty+i, r = by+tx;
        if (c<Cc && r<R) outb[(size_t)c*R + r] = tile[tx][ty+i];
    }
}

// ---------------- depthwise 3x3 s2 conv + LayerNorm + GELU ----------------
__global__ __launch_bounds__(384) void dwln_kernel(
    const float* __restrict__ Wdw, const float* __restrict__ bdw,
    const float* __restrict__ ln_g, const float* __restrict__ ln_b)
{
    __shared__ float red[13];
    int p = blockIdx.x;        // b*49 + s
    int b = p/49, s = p - b*49;
    int oy = s/7, ox = s - oy*7;
    int c = threadIdx.x;       // 0..383
    float acc = bdw[c];
    #pragma unroll
    for (int kh=0;kh<3;kh++){
        int iy = oy*2-1+kh;
        if (iy<0 || iy>=14) continue;
        #pragma unroll
        for (int kw=0;kw<3;kw++){
            int ix = ox*2-1+kw;
            if (ix<0 || ix>=14) continue;
            acc += g_t1[((b*196)+iy*14+ix)*384 + c]*Wdw[c*9+kh*3+kw];
        }
    }
    int lane = c & 31, w = c >> 5;
    // mean
    float t = acc;
    #pragma unroll
    for (int o=16;o;o>>=1) t += __shfl_xor_sync(0xffffffffu, t, o);
    if (lane==0) red[w] = t;
    __syncthreads();
    if (w==0){
        float u = (lane<12)? red[lane] : 0.f;
        #pragma unroll
        for (int o=16;o;o>>=1) u += __shfl_xor_sync(0xffffffffu, u, o);
        if (lane==0) red[12] = u;
    }
    __syncthreads();
    float mu = red[12] * (1.0f/384.0f);
    __syncthreads();
    // var
    float d = acc - mu;
    t = d*d;
    #pragma unroll
    for (int o=16;o;o>>=1) t += __shfl_xor_sync(0xffffffffu, t, o);
    if (lane==0) red[w] = t;
    __syncthreads();
    if (w==0){
        float u = (lane<12)? red[lane] : 0.f;
        #pragma unroll
        for (int o=16;o;o>>=1) u += __shfl_xor_sync(0xffffffffu, u, o);
        if (lane==0) red[12] = u;
    }
    __syncthreads();
    float var = red[12]*(1.0f/384.0f);
    float tn = d * rsqrtf(var + 1e-5f) * ln_g[c] + ln_b[c];
    g_t2[p*384 + c] = gelu_f(tn);
}

// ---------------- fused deformable attention: one block per token ---------
// Gathers 58x384 feats in SMEM, computes bias+attn+softmax, writes fa.
__global__ __launch_bounds__(384) void attn_kernel(
    const float* __restrict__ bk, const float* __restrict__ posembed)
{
    extern __shared__ float smarr[];
    float* feats = smarr;                 // ST_*FSTR
    float* attnS = feats + ST_*FSTR;      // 12*64
    float* sw    = attnS + 12*64;         // ST_*4
    float* bpy   = sw + ST_*4;            // ST_
    float* bpx   = bpy + ST_;             // ST_
    float* qbks  = bpx + ST_;             // 12
    int*   sa    = (int*)(qbks + 12);     // ST_*4

    int m = blockIdx.x;
    int b = m / 196, n = m - b*196;
    int ny = n / 14, nx = n - ny*14;
    int tid = threadIdx.x;
    int lane = tid & 31, wid = tid >> 5;

    // per-slot sampling setup
    if (tid < ST_){
        int s = tid;
        float py, px, by, bx;
        if (s < S_){
            int ry = s/7, rx = s - ry*7;
            float offY = g_offp[(b*49+s)*392 + n];
            float offX = g_offp[(b*49+s)*392 + 196 + n];
            float gy = (2.0f*ry)*(2.0f/13.0f) - 1.0f;
            float gx = (2.0f*rx)*(2.0f/13.0f) - 1.0f;
            py = (offY + gy + 1.0f)*6.5f;
            px = (offX + gx + 1.0f)*6.5f;
            by = ((2.0f*ry - (float)ny)*(1.0f/13.0f) - offY + 1.0f)*13.0f;
            bx = ((2.0f*rx - (float)nx)*(1.0f/13.0f) - offX + 1.0f)*13.0f;
        } else {
            int kk = s - S_;
            float coY = g_co[m*18 + kk*2];
            float coX = g_co[m*18 + kk*2 + 1];
            float cpy = fminf(fmaxf((float)ny + c_offy[kk], 0.f), 14.f);
            float cpx = fminf(fmaxf((float)nx + c_offx[kk], 0.f), 14.f);
            float cgy = cpy*(2.0f/13.0f) - 1.0f;
            float cgx = cpx*(2.0f/13.0f) - 1.0f;
            py = (coY + cgy + 1.0f)*6.5f;
            px = (coX + cgx + 1.0f)*6.5f;
            by = (coY - (float)ny + 1.0f)*13.0f;
            bx = (coX - (float)nx + 1.0f)*13.0f;
        }
        bpy[s] = by; bpx[s] = bx;
        float y0f = floorf(py), x0f = floorf(px);
        float wy1 = py - y0f, wx1 = px - x0f;
        int y0 = (int)y0f, x0 = (int)x0f;
        float wts[4] = {(1.f-wy1)*(1.f-wx1), (1.f-wy1)*wx1, wy1*(1.f-wx1), wy1*wx1};
        const int dys[4] = {0,0,1,1};
        const int dxs[4] = {0,1,0,1};
        #pragma unroll
        for (int i=0;i<4;i++){
            int yy = y0+dys[i], xx = x0+dxs[i];
            bool valid = (yy>=0 && yy<=13 && xx>=0 && xx<=13);
            int yc = min(max(yy,0),13), xc = min(max(xx,0),13);
            sw[s*4+i] = valid ? wts[i] : 0.f;
            sa[s*4+i] = ((b*196) + yc*14 + xc)*384;
        }
    }
    // q . bk per head
    if (tid < 12){
        float acc = 0.f;
        #pragma unroll 8
        for (int d=0; d<32; d++)
            acc += g_q[m*384 + tid*32 + d]*bk[tid*32 + d];
        qbks[tid] = acc;
    }
    __syncthreads();

    // fill feats (all threads share the same slot each iteration -> coalesced)
    {
        int c = tid;
        for (int i=0;i<ST_;i++){
            float v = sw[i*4+0]*g_xh[sa[i*4+0]+c]
                    + sw[i*4+1]*g_xh[sa[i*4+1]+c]
                    + sw[i*4+2]*g_xh[sa[i*4+2]+c]
                    + sw[i*4+3]*g_xh[sa[i*4+3]+c];
            feats[i*FSTR + c] = v;
        }
    }
    // relative position bias via bilinear into 27x27xHEADS table
    for (int p2 = tid; p2 < 12*ST_; p2 += 384){
        int h = p2 / ST_, s = p2 - h*ST_;
        float py = bpy[s], px = bpx[s];
        float y0f = floorf(py), x0f = floorf(px);
        float wy1 = py - y0f, wx1 = px - x0f;
        int y0 = (int)y0f, x0 = (int)x0f;
        const float* tb = posembed + h*729;
        float acc = 0.f;
        float wts[4] = {(1.f-wy1)*(1.f-wx1), (1.f-wy1)*wx1, wy1*(1.f-wx1), wy1*wx1};
        const int dys[4]={0,0,1,1}, dxs[4]={0,1,0,1};
        #pragma unroll
        for (int i=0;i<4;i++){
            int yy=y0+dys[i], xx=x0+dxs[i];
            if (yy>=0 && yy<=26 && xx>=0 && xx<=26)
                acc += tb[yy*27+xx]*wts[i];
        }
        attnS[h*64+s] = acc;
    }
    __syncthreads();

    // attention logits: warp wid = head wid, whole warp per (h,s) dot
    {
        float qkreg[12];
        const float* qkp = g_qk + ((size_t)m*12 + wid)*384;
        #pragma unroll
        for (int i=0;i<12;i++) qkreg[i] = qkp[lane + 32*i];
        float qb = qbks[wid];
        for (int s=0;s<ST_;s++){
            const float* f = feats + s*FSTR;
            float acc = 0.f;
            #pragma unroll
            for (int i=0;i<12;i++) acc += qkreg[i]*f[lane+32*i];
            #pragma unroll
            for (int o=16;o;o>>=1) acc += __shfl_xor_sync(0xffffffffu, acc, o);
            if (lane==0) attnS[wid*64+s] += acc + qb;
        }
    }
    __syncwarp();
    // softmax over 58 per head (warp-local)
    {
        float v0 = attnS[wid*64 + lane];
        float v1 = (lane < ST_-32) ? attnS[wid*64 + 32 + lane] : -1e30f;
        float mx = fmaxf(v0, v1);
        #pragma unroll
        for (int o=16;o;o>>=1) mx = fmaxf(mx, __shfl_xor_sync(0xffffffffu, mx, o));
        float e0 = expf(v0 - mx);
        float e1 = (lane < ST_-32) ? expf(v1 - mx) : 0.f;
        float ssum = e0 + e1;
        #pragma unroll
        for (int o=16;o;o>>=1) ssum += __shfl_xor_sync(0xffffffffu, ssum, o);
        float inv = 1.0f/ssum;
        attnS[wid*64 + lane] = e0*inv;
        if (lane < ST_-32) attnS[wid*64+32+lane] = e1*inv;
    }
    __syncthreads();
    // fa[h][c] = sum_s attn[h][s] * feats[s][c]
    {
        int c = tid;
        float acc[12];
        #pragma unroll
        for (int h=0;h<12;h++) acc[h]=0.f;
        for (int s=0;s<ST_;s++){
            float f = feats[s*FSTR + c];
            #pragma unroll
            for (int h=0;h<12;h++) acc[h] += attnS[h*64+s]*f;
        }
        #pragma unroll
        for (int h=0;h<12;h++)
            g_fa[((size_t)m*12+h)*384 + c] = acc[h];
    }
}

// ---------------------------------------------------------------------------
extern "C" void kernel_launch(void* const* d_in, const int* in_sizes, int n_in,
                              void* d_out, int out_size)
{
    (void)in_sizes; (void)n_in; (void)out_size;
    const float* x   = (const float*)d_in[0];
    const float* Wq  = (const float*)d_in[1];
    const float* bq  = (const float*)d_in[2];
    const float* Wk  = (const float*)d_in[3];
    const float* bk  = (const float*)d_in[4];
    const float* Wv  = (const float*)d_in[5];
    const float* bv  = (const float*)d_in[6];
    const float* Wo1 = (const float*)d_in[7];
    const float* bo1 = (const float*)d_in[8];
    const float* Wdw = (const float*)d_in[9];
    const float* bdw = (const float*)d_in[10];
    const float* ln_g= (const float*)d_in[11];
    const float* ln_b= (const float*)d_in[12];
    const float* Wo2 = (const float*)d_in[13];
    const float* Wco = (const float*)d_in[14];
    const float* pe  = (const float*)d_in[15];
    const float* Wp  = (const float*)d_in[16];
    const float* bp  = (const float*)d_in[17];
    float* out = (float*)d_out;

    float *xh,*q,*t1,*t2,*offp,*co,*qk,*fa,*ov,*y;
    cudaGetSymbolAddress((void**)&xh,  g_xh);
    cudaGetSymbolAddress((void**)&q,   g_q);
    cudaGetSymbolAddress((void**)&t1,  g_t1);
    cudaGetSymbolAddress((void**)&t2,  g_t2);
    cudaGetSymbolAddress((void**)&offp,g_offp);
    cudaGetSymbolAddress((void**)&co,  g_co);
    cudaGetSymbolAddress((void**)&qk,  g_qk);
    cudaGetSymbolAddress((void**)&fa,  g_fa);
    cudaGetSymbolAddress((void**)&ov,  g_ov);
    cudaGetSymbolAddress((void**)&y,   g_y);

    const int SMEM_BYTES = (ST_*FSTR + 12*64 + ST_*4 + ST_ + ST_ + 12 + ST_*4)*4;
    cudaFuncSetAttribute(attn_kernel,
                         cudaFuncAttributeMaxDynamicSharedMemorySize, SMEM_BYTES);

    dim3 tb(32,8);

    // 1) x (B,C,H,W) -> xh (B,N,C)
    transpose_kernel<<<dim3(CDIV(196,32), CDIV(384,32), B_), tb>>>(x, xh, 384, 196);

    // 2) q = xh @ Wq^T + bq
    gemm_kernel<<<dim3(6,25,1),256>>>(xh, Wq, bq, q, M_,384,384, 384,384,384,
                                      0,0,0,0, 1, 0, 0.f);
    // 3) t1 = gelu(q @ Wo1^T + bo1)
    gemm_kernel<<<dim3(6,25,1),256>>>(q, Wo1, bo1, t1, M_,384,384, 384,384,384,
                                      0,0,0,0, 1, 1, 0.f);
    // 4) depthwise conv + LN + gelu -> t2
    dwln_kernel<<<B_*S_, 384>>>(Wdw, bdw, ln_g, ln_b);

    // 5) offp = tanh(t2 @ Wo2^T) * FACTOR/14
    gemm_kernel<<<dim3(7,7,1),256>>>(t2, Wo2, nullptr, offp, B_*S_, 392, 384,
                                     384,384,392, 0,0,0,0, 1, 2, 2.0f/14.0f);
    // 6) co = tanh(q @ Wco^T) * 1/14
    gemm_kernel<<<dim3(1,25,1),256>>>(q, Wco, nullptr, co, M_, 18, 384,
                                      384,384,18, 0,0,0,0, 1, 2, 1.0f/14.0f);
    // 7) qk[m,h,c] = sum_d q[m,h*32+d] * Wk[h*32+d, c]   (batched over heads)
    gemm_kernel<<<dim3(6,25,12),256>>>(q, Wk, nullptr, qk, M_, 384, 32,
                                       384,384,12*384,
                                       32LL, 32LL*384, 384LL, 0, 0, 0, 0.f);
    // 8) fused deformable attention -> fa
    attn_kernel<<<M_, 384, SMEM_BYTES>>>(bk, pe);

    // 9) ov[m,h*32+d] = sum_c fa[m,h,c]*Wv[h*32+d,c] + bv  (batched over heads)
    gemm_kernel<<<dim3(1,25,12),256>>>(fa, Wv, bv, ov, M_, 32, 384,
                                       12*384,384,384,
                                       384LL, 32LL*384, 32LL, 32, 1, 0, 0.f);
    // 10) y = ov @ Wp^T + bp
    gemm_kernel<<<dim3(6,25,1),256>>>(ov, Wp, bp, y, M_,384,384, 384,384,384,
                                      0,0,0,0, 1, 0, 0.f);
    // 11) y (B,N,C) -> out (B,C,H,W)
    transpose_kernel<<<dim3(CDIV(384,32), CDIV(196,32), B_), tb>>>(y, out, 196, 384);
}

// round 2
// speedup vs baseline: 1.7044x; 1.7044x over previous
#include <cuda_runtime.h>
#include <math.h>

#define B_ 8
#define C_ 384
#define H_ 14
#define W_ 14
#define N_ 196
#define HEADS_ 12
#define RH_ 7
#define RW_ 7
#define S_ 49
#define ST_ 58
#define M_ (B_*N_)     // 1568
#define FSTR 388       // padded feats row stride (float4-aligned)

#define CDIV(a,b) (((a)+(b)-1)/(b))

// ---------------- scratch (device globals; no allocation allowed) ----------
__device__ float g_xh[M_*C_];
__device__ float g_q [M_*C_];
__device__ float g_t1[M_*C_];
__device__ float g_t2[B_*S_*C_];
__device__ float g_offp[B_*S_*2*N_];
__device__ float g_co[M_*18];
__device__ float g_qk[(size_t)M_*HEADS_*C_];
__device__ float g_fa[(size_t)M_*HEADS_*C_];
__device__ float g_ov[M_*C_];
__device__ float g_y [M_*C_];

__constant__ float c_offy[9] = {0.f,-1.f,-1.f,-1.f,0.f,1.f,1.f,1.f,0.f};
__constant__ float c_offx[9] = {-1.f,-1.f,0.f,1.f,1.f,1.f,0.f,-1.f,0.f};

__device__ __forceinline__ float gelu_f(float v){
    return 0.5f*v*(1.0f+erff(v*0.70710678118654752f));
}

// ---------------- templated batched tiled GEMM:  C = A * op(B) (+bias)(+ep)
// A row-major [M,K]. !transB: B[k,n]=Bm[k*ldb+n]. transB: B[k,n]=Bm[n*ldb+k].
// K must be a multiple of 16. lda/ldb and base pointers must be float4-aligned.
// ep: 0 none, 1 gelu, 2 tanh*scale
template<int BM, int BN>
__global__ __launch_bounds__((BM/4)*(BN/4)) void gemm_t(
    const float* __restrict__ A, const float* __restrict__ Bm,
    const float* __restrict__ bias, float* __restrict__ C,
    int M, int N, int K, int lda, int ldb, int ldc,
    long long aB, long long bB, long long cB, int biasB,
    int transB, int ep, float scale)
{
    constexpr int T  = (BM/4)*(BN/4);
    constexpr int NA = (BM*4)/T;          // float4 loads of A per thread
    constexpr int NB = (BN*4)/T;          // float4 loads of B per thread
    __shared__ float As[16][BM+4];
    __shared__ float Bs[16][BN+4];

    A  += (long long)blockIdx.z * aB;
    Bm += (long long)blockIdx.z * bB;
    C  += (long long)blockIdx.z * cB;
    if (bias) bias += (long long)blockIdx.z * biasB;

    const int m0 = blockIdx.y*BM, n0 = blockIdx.x*BN;
    const int tid = threadIdx.x;
    const int tx = tid % (BN/4), ty = tid / (BN/4);

    float acc[4][4];
    #pragma unroll
    for (int i=0;i<4;i++)
        #pragma unroll
        for (int j=0;j<4;j++) acc[i][j]=0.f;

    float4 pa[NA], pb[NB];
    const float4 z4 = make_float4(0.f,0.f,0.f,0.f);

    auto loadT = [&](int k0){
        #pragma unroll
        for (int u=0;u<NA;u++){
            int f = tid + u*T;
            int r = f>>2, kc = (f&3)*4;
            int mm = m0 + r;
            pa[u] = (mm<M) ? *(const float4*)&A[(long long)mm*lda + k0 + kc] : z4;
        }
        if (transB){
            #pragma unroll
            for (int u=0;u<NB;u++){
                int f = tid + u*T;
                int r = f>>2, kc = (f&3)*4;
                int nn = n0 + r;
                pb[u] = (nn<N) ? *(const float4*)&Bm[(long long)nn*ldb + k0 + kc] : z4;
            }
        } else {
            #pragma unroll
            for (int u=0;u<NB;u++){
                int f = tid + u*T;
                int kk = f/(BN/4), nc = (f%(BN/4))*4;
                int nn = n0 + nc;
                pb[u] = (nn<N) ? *(const float4*)&Bm[(long long)(k0+kk)*ldb + nn] : z4;
            }
        }
    };
    auto storeT = [&](){
        #pragma unroll
        for (int u=0;u<NA;u++){
            int f = tid + u*T;
            int r = f>>2, kc = (f&3)*4;
            As[kc+0][r]=pa[u].x; As[kc+1][r]=pa[u].y;
            As[kc+2][r]=pa[u].z; As[kc+3][r]=pa[u].w;
        }
        if (transB){
            #pragma unroll
            for (int u=0;u<NB;u++){
                int f = tid + u*T;
                int r = f>>2, kc = (f&3)*4;
                Bs[kc+0][r]=pb[u].x; Bs[kc+1][r]=pb[u].y;
                Bs[kc+2][r]=pb[u].z; Bs[kc+3][r]=pb[u].w;
            }
        } else {
            #pragma unroll
            for (int u=0;u<NB;u++){
                int f = tid + u*T;
                int kk = f/(BN/4), nc = (f%(BN/4))*4;
                *(float4*)&Bs[kk][nc] = pb[u];
            }
        }
    };

    loadT(0); storeT(); __syncthreads();
    for (int k0=16; k0<=K; k0+=16){
        bool more = (k0 < K);
        if (more) loadT(k0);
        #pragma unroll
        for (int k=0;k<16;k++){
            float4 a = *(const float4*)&As[k][ty*4];
            float4 b = *(const float4*)&Bs[k][tx*4];
            acc[0][0] += a.x*b.x; acc[0][1] += a.x*b.y; acc[0][2] += a.x*b.z; acc[0][3] += a.x*b.w;
            acc[1][0] += a.y*b.x; acc[1][1] += a.y*b.y; acc[1][2] += a.y*b.z; acc[1][3] += a.y*b.w;
            acc[2][0] += a.z*b.x; acc[2][1] += a.z*b.y; acc[2][2] += a.z*b.z; acc[2][3] += a.z*b.w;
            acc[3][0] += a.w*b.x; acc[3][1] += a.w*b.y; acc[3][2] += a.w*b.z; acc[3][3] += a.w*b.w;
        }
        __syncthreads();
        if (more){ storeT(); __syncthreads(); }
    }

    #pragma unroll
    for (int i=0;i<4;i++){
        int mm = m0 + ty*4 + i;
        if (mm>=M) continue;
        #pragma unroll
        for (int j=0;j<4;j++){
            int nn = n0 + tx*4 + j;
            if (nn>=N) continue;
            float v = acc[i][j];
            if (bias) v += bias[nn];
            if (ep==1) v = gelu_f(v);
            else if (ep==2) v = tanhf(v)*scale;
            C[(long long)mm*ldc + nn] = v;
        }
    }
}

// ---------------- batched matrix transpose: in [R,Cc] -> out [Cc,R] --------
__global__ __launch_bounds__(256) void transpose_kernel(
    const float* __restrict__ in, float* __restrict__ out, int R, int Cc)
{
    __shared__ float tile[32][33];
    const float* inb = in + (size_t)blockIdx.z * R * Cc;
    float* outb = out + (size_t)blockIdx.z * R * Cc;
    int bx = blockIdx.x*32, by = blockIdx.y*32;
    int tx = threadIdx.x, ty = threadIdx.y;
    #pragma unroll
    for (int i=0;i<32;i+=8){
        int r = by+ty+i, c = bx+tx;
        if (r<R && c<Cc) tile[ty+i][tx] = inb[(size_t)r*Cc + c];
    }
    __syncthreads();
    #pragma unroll
    for (int i=0;i<32;i+=8){
        int c = bx+ty+i, r = by+tx;
        if (c<Cc && r<R) outb[(size_t)c*R + r] = tile[tx][ty+i];
    }
}

// ---------------- depthwise 3x3 s2 conv + LayerNorm + GELU ----------------
__global__ __launch_bounds__(384) void dwln_kernel(
    const float* __restrict__ Wdw, const float* __restrict__ bdw,
    const float* __restrict__ ln_g, const float* __restrict__ ln_b)
{
    __shared__ float red[13];
    int p = blockIdx.x;        // b*49 + s
    int b = p/49, s = p - b*49;
    int oy = s/7, ox = s - oy*7;
    int c = threadIdx.x;       // 0..383
    float acc = bdw[c];
    #pragma unroll
    for (int kh=0;kh<3;kh++){
        int iy = oy*2-1+kh;
        if (iy<0 || iy>=14) continue;
        #pragma unroll
        for (int kw=0;kw<3;kw++){
            int ix = ox*2-1+kw;
            if (ix<0 || ix>=14) continue;
            acc += g_t1[((b*196)+iy*14+ix)*384 + c]*Wdw[c*9+kh*3+kw];
        }
    }
    int lane = c & 31, w = c >> 5;
    float t = acc;
    #pragma unroll
    for (int o=16;o;o>>=1) t += __shfl_xor_sync(0xffffffffu, t, o);
    if (lane==0) red[w] = t;
    __syncthreads();
    if (w==0){
        float u = (lane<12)? red[lane] : 0.f;
        #pragma unroll
        for (int o=16;o;o>>=1) u += __shfl_xor_sync(0xffffffffu, u, o);
        if (lane==0) red[12] = u;
    }
    __syncthreads();
    float mu = red[12] * (1.0f/384.0f);
    __syncthreads();
    float d = acc - mu;
    t = d*d;
    #pragma unroll
    for (int o=16;o;o>>=1) t += __shfl_xor_sync(0xffffffffu, t, o);
    if (lane==0) red[w] = t;
    __syncthreads();
    if (w==0){
        float u = (lane<12)? red[lane] : 0.f;
        #pragma unroll
        for (int o=16;o;o>>=1) u += __shfl_xor_sync(0xffffffffu, u, o);
        if (lane==0) red[12] = u;
    }
    __syncthreads();
    float var = red[12]*(1.0f/384.0f);
    float tn = d * rsqrtf(var + 1e-5f) * ln_g[c] + ln_b[c];
    g_t2[p*384 + c] = gelu_f(tn);
}

// ---------------- fused deformable attention: one block per token ---------
__global__ __launch_bounds__(384,2) void attn_kernel(
    const float* __restrict__ bk, const float* __restrict__ posembed)
{
    extern __shared__ float smarr[];
    float* feats = smarr;                 // ST_*FSTR
    float* attnS = feats + ST_*FSTR;      // 12*64
    float* sw    = attnS + 12*64;         // ST_*4
    float* bpy   = sw + ST_*4;            // ST_
    float* bpx   = bpy + ST_;             // ST_
    float* qbks  = bpx + ST_;             // 12
    int*   sa    = (int*)(qbks + 12);     // ST_*4

    int m = blockIdx.x;
    int b = m / 196, n = m - b*196;
    int ny = n / 14, nx = n - ny*14;
    int tid = threadIdx.x;
    int lane = tid & 31, wid = tid >> 5;

    // per-slot sampling setup
    if (tid < ST_){
        int s = tid;
        float py, px, by, bx;
        if (s < S_){
            int ry = s/7, rx = s - ry*7;
            float offY = g_offp[(b*49+s)*392 + n];
            float offX = g_offp[(b*49+s)*392 + 196 + n];
            float gy = (2.0f*ry)*(2.0f/13.0f) - 1.0f;
            float gx = (2.0f*rx)*(2.0f/13.0f) - 1.0f;
            py = (offY + gy + 1.0f)*6.5f;
            px = (offX + gx + 1.0f)*6.5f;
            by = ((2.0f*ry - (float)ny)*(1.0f/13.0f) - offY + 1.0f)*13.0f;
            bx = ((2.0f*rx - (float)nx)*(1.0f/13.0f) - offX + 1.0f)*13.0f;
        } else {
            int kk = s - S_;
            float coY = g_co[m*18 + kk*2];
            float coX = g_co[m*18 + kk*2 + 1];
            float cpy = fminf(fmaxf((float)ny + c_offy[kk], 0.f), 14.f);
            float cpx = fminf(fmaxf((float)nx + c_offx[kk], 0.f), 14.f);
            float cgy = cpy*(2.0f/13.0f) - 1.0f;
            float cgx = cpx*(2.0f/13.0f) - 1.0f;
            py = (coY + cgy + 1.0f)*6.5f;
            px = (coX + cgx + 1.0f)*6.5f;
            by = (coY - (float)ny + 1.0f)*13.0f;
            bx = (coX - (float)nx + 1.0f)*13.0f;
        }
        bpy[s] = by; bpx[s] = bx;
        float y0f = floorf(py), x0f = floorf(px);
        float wy1 = py - y0f, wx1 = px - x0f;
        int y0 = (int)y0f, x0 = (int)x0f;
        float wts[4] = {(1.f-wy1)*(1.f-wx1), (1.f-wy1)*wx1, wy1*(1.f-wx1), wy1*wx1};
        const int dys[4] = {0,0,1,1};
        const int dxs[4] = {0,1,0,1};
        #pragma unroll
        for (int i=0;i<4;i++){
            int yy = y0+dys[i], xx = x0+dxs[i];
            bool valid = (yy>=0 && yy<=13 && xx>=0 && xx<=13);
            int yc = min(max(yy,0),13), xc = min(max(xx,0),13);
            sw[s*4+i] = valid ? wts[i] : 0.f;
            sa[s*4+i] = ((b*196) + yc*14 + xc)*384;
        }
    }
    // q . bk per head
    if (tid < 12){
        float acc = 0.f;
        #pragma unroll 8
        for (int d=0; d<32; d++)
            acc += g_q[m*384 + tid*32 + d]*bk[tid*32 + d];
        qbks[tid] = acc;
    }
    __syncthreads();

    // fill feats: float4 gather, 4 slot-groups in flight
    {
        int cg = tid % 96;               // c4 group
        int g  = tid / 96;               // slot group 0..3
        int c4 = cg * 4;
        for (int s = g; s < ST_; s += 4){
            float w0 = sw[s*4+0], w1 = sw[s*4+1], w2 = sw[s*4+2], w3 = sw[s*4+3];
            const float4 v0 = *(const float4*)&g_xh[sa[s*4+0] + c4];
            const float4 v1 = *(const float4*)&g_xh[sa[s*4+1] + c4];
            const float4 v2 = *(const float4*)&g_xh[sa[s*4+2] + c4];
            const float4 v3 = *(const float4*)&g_xh[sa[s*4+3] + c4];
            float4 r;
            r.x = w0*v0.x + w1*v1.x + w2*v2.x + w3*v3.x;
            r.y = w0*v0.y + w1*v1.y + w2*v2.y + w3*v3.y;
            r.z = w0*v0.z + w1*v1.z + w2*v2.z + w3*v3.z;
            r.w = w0*v0.w + w1*v1.w + w2*v2.w + w3*v3.w;
            *(float4*)&feats[s*FSTR + c4] = r;
        }
    }
    // relative position bias via bilinear into 27x27xHEADS table
    for (int p2 = tid; p2 < 12*ST_; p2 += 384){
        int h = p2 / ST_, s = p2 - h*ST_;
        float py = bpy[s], px = bpx[s];
        float y0f = floorf(py), x0f = floorf(px);
        float wy1 = py - y0f, wx1 = px - x0f;
        int y0 = (int)y0f, x0 = (int)x0f;
        const float* tb = posembed + h*729;
        float acc = 0.f;
        float wts[4] = {(1.f-wy1)*(1.f-wx1), (1.f-wy1)*wx1, wy1*(1.f-wx1), wy1*wx1};
        const int dys[4]={0,0,1,1}, dxs[4]={0,1,0,1};
        #pragma unroll
        for (int i=0;i<4;i++){
            int yy=y0+dys[i], xx=x0+dxs[i];
            if (yy>=0 && yy<=26 && xx>=0 && xx<=26)
                acc += tb[yy*27+xx]*wts[i];
        }
        attnS[h*64+s] = acc;
    }
    __syncthreads();

    // attention logits: 2 heads per warp, slots split in halves.
    // Each feats read serves 2 heads -> half the LDS bytes.
    {
        int hp   = wid % 6;          // head pair
        int half = wid / 6;          // slot half
        int h0 = 2*hp, h1 = h0+1;
        float qk0[12], qk1[12];
        const float* qp0 = g_qk + ((size_t)m*12 + h0)*384;
        const float* qp1 = g_qk + ((size_t)m*12 + h1)*384;
        #pragma unroll
        for (int i=0;i<12;i++){ qk0[i] = qp0[lane + 32*i]; qk1[i] = qp1[lane + 32*i]; }
        float qb0 = qbks[h0], qb1 = qbks[h1];
        int s0 = half*29;
        for (int s = s0; s < s0+29; s++){
            const float* f = feats + s*FSTR;
            float a0 = 0.f, a1 = 0.f;
            #pragma unroll
            for (int i=0;i<12;i++){
                float fv = f[lane + 32*i];
                a0 += qk0[i]*fv;
                a1 += qk1[i]*fv;
            }
            #pragma unroll
            for (int o=16;o;o>>=1){
                a0 += __shfl_xor_sync(0xffffffffu, a0, o);
                a1 += __shfl_xor_sync(0xffffffffu, a1, o);
            }
            if (lane==0){
                attnS[h0*64+s] += a0 + qb0;
                attnS[h1*64+s] += a1 + qb1;
            }
        }
    }
    __syncthreads();
    // softmax over 58 per head (warp wid handles head wid)
    {
        float v0 = attnS[wid*64 + lane];
        float v1 = (lane < ST_-32) ? attnS[wid*64 + 32 + lane] : -1e30f;
        float mx = fmaxf(v0, v1);
        #pragma unroll
        for (int o=16;o;o>>=1) mx = fmaxf(mx, __shfl_xor_sync(0xffffffffu, mx, o));
        float e0 = expf(v0 - mx);
        float e1 = (lane < ST_-32) ? expf(v1 - mx) : 0.f;
        float ssum = e0 + e1;
        #pragma unroll
        for (int o=16;o;o>>=1) ssum += __shfl_xor_sync(0xffffffffu, ssum, o);
        float inv = 1.0f/ssum;
        attnS[wid*64 + lane] = e0*inv;
        if (lane < ST_-32) attnS[wid*64+32+lane] = e1*inv;
    }
    __syncthreads();
    // fa[h][c] = sum_s attn[h][s] * feats[s][c]
    {
        int c = tid;
        float acc[12];
        #pragma unroll
        for (int h=0;h<12;h++) acc[h]=0.f;
        for (int s=0;s<ST_;s++){
            float f = feats[s*FSTR + c];
            #pragma unroll
            for (int h=0;h<12;h++) acc[h] += attnS[h*64+s]*f;
        }
        #pragma unroll
        for (int h=0;h<12;h++)
            g_fa[((size_t)m*12+h)*384 + c] = acc[h];
    }
}

// ---------------------------------------------------------------------------
extern "C" void kernel_launch(void* const* d_in, const int* in_sizes, int n_in,
                              void* d_out, int out_size)
{
    (void)in_sizes; (void)n_in; (void)out_size;
    const float* x   = (const float*)d_in[0];
    const float* Wq  = (const float*)d_in[1];
    const float* bq  = (const float*)d_in[2];
    const float* Wk  = (const float*)d_in[3];
    const float* bk  = (const float*)d_in[4];
    const float* Wv  = (const float*)d_in[5];
    const float* bv  = (const float*)d_in[6];
    const float* Wo1 = (const float*)d_in[7];
    const float* bo1 = (const float*)d_in[8];
    const float* Wdw = (const float*)d_in[9];
    const float* bdw = (const float*)d_in[10];
    const float* ln_g= (const float*)d_in[11];
    const float* ln_b= (const float*)d_in[12];
    const float* Wo2 = (const float*)d_in[13];
    const float* Wco = (const float*)d_in[14];
    const float* pe  = (const float*)d_in[15];
    const float* Wp  = (const float*)d_in[16];
    const float* bp  = (const float*)d_in[17];
    float* out = (float*)d_out;

    float *xh,*q,*t1,*t2,*offp,*co,*qk,*fa,*ov,*y;
    cudaGetSymbolAddress((void**)&xh,  g_xh);
    cudaGetSymbolAddress((void**)&q,   g_q);
    cudaGetSymbolAddress((void**)&t1,  g_t1);
    cudaGetSymbolAddress((void**)&t2,  g_t2);
    cudaGetSymbolAddress((void**)&offp,g_offp);
    cudaGetSymbolAddress((void**)&co,  g_co);
    cudaGetSymbolAddress((void**)&qk,  g_qk);
    cudaGetSymbolAddress((void**)&fa,  g_fa);
    cudaGetSymbolAddress((void**)&ov,  g_ov);
    cudaGetSymbolAddress((void**)&y,   g_y);

    const int SMEM_BYTES = (ST_*FSTR + 12*64 + ST_*4 + ST_ + ST_ + 12 + ST_*4)*4;
    cudaFuncSetAttribute(attn_kernel,
                         cudaFuncAttributeMaxDynamicSharedMemorySize, SMEM_BYTES);

    dim3 tb(32,8);

    // 1) x (B,C,H,W) -> xh (B,N,C)
    transpose_kernel<<<dim3(CDIV(196,32), CDIV(384,32), B_), tb>>>(x, xh, 384, 196);

    // 2) q = xh @ Wq^T + bq
    gemm_t<64,64><<<dim3(6,25,1),256>>>(xh, Wq, bq, q, M_,384,384, 384,384,384,
                                        0,0,0,0, 1, 0, 0.f);
    // 3) t1 = gelu(q @ Wo1^T + bo1)
    gemm_t<64,64><<<dim3(6,25,1),256>>>(q, Wo1, bo1, t1, M_,384,384, 384,384,384,
                                        0,0,0,0, 1, 1, 0.f);
    // 4) depthwise conv + LN + gelu -> t2
    dwln_kernel<<<B_*S_, 384>>>(Wdw, bdw, ln_g, ln_b);

    // 5) offp = tanh(t2 @ Wo2^T) * FACTOR/14
    gemm_t<32,32><<<dim3(13,13,1),64>>>(t2, Wo2, nullptr, offp, B_*S_, 392, 384,
                                        384,384,392, 0,0,0,0, 1, 2, 2.0f/14.0f);
    // 6) co = tanh(q @ Wco^T) * 1/14
    gemm_t<32,32><<<dim3(1,49,1),64>>>(q, Wco, nullptr, co, M_, 18, 384,
                                       384,384,18, 0,0,0,0, 1, 2, 1.0f/14.0f);
    // 7) qk[m,h,c] = sum_d q[m,h*32+d] * Wk[h*32+d, c]   (batched over heads)
    gemm_t<64,64><<<dim3(6,25,12),256>>>(q, Wk, nullptr, qk, M_, 384, 32,
                                         384,384,12*384,
                                         32LL, 32LL*384, 384LL, 0, 0, 0, 0.f);
    // 8) fused deformable attention -> fa
    attn_kernel<<<M_, 384, SMEM_BYTES>>>(bk, pe);

    // 9) ov[m,h*32+d] = sum_c fa[m,h,c]*Wv[h*32+d,c] + bv  (batched over heads)
    gemm_t<64,32><<<dim3(1,25,12),128>>>(fa, Wv, bv, ov, M_, 32, 384,
                                         12*384,384,384,
                                         384LL, 32LL*384, 32LL, 32, 1, 0, 0.f);
    // 10) y = ov @ Wp^T + bp
    gemm_t<64,64><<<dim3(6,25,1),256>>>(ov, Wp, bp, y, M_,384,384, 384,384,384,
                                        0,0,0,0, 1, 0, 0.f);
    // 11) y (B,N,C) -> out (B,C,H,W)
    transpose_kernel<<<dim3(CDIV(384,32), CDIV(196,32), B_), tb>>>(y, out, 196, 384);
}